// round 3
// baseline (speedup 1.0000x reference)
#include <cuda_runtime.h>
#include <cuda_fp16.h>
#include <cstdint>

#define NN     2048
#define NODES  4096
#define LOG2E  1.4426950408889634f

// ---------------- device scratch ----------------
__device__ __align__(16) __half g_d[(size_t)NODES * NN];  // (F1-F0)*log2e, fp16, 16.8MB
__device__ __align__(16) float  g_s1[2][NODES];           // s1 ping-pong tables
__device__ __align__(16) float  g_A[NODES];               // sum_y qF1 * s0cur[y]
__device__ __align__(16) float  g_Bv[NODES];              // sum_x qF1 * s1cur[x]

__device__ __forceinline__ float ex2f(float x) {
    float r; asm("ex2.approx.f32 %0, %1;" : "=f"(r) : "f"(x)); return r;
}
// 1/(1+u), u>=0 finite: magic seed + 2 Newton steps (rel err ~1.4e-6)
__device__ __forceinline__ float rcp1p(float u) {
    float den = 1.0f + u;
    float r = __uint_as_float(0x7ef311c3u - __float_as_uint(den));
    r = r * (2.0f - den * r);
    r = r * (2.0f - den * r);
    return r;
}
__device__ __forceinline__ float sigl(float zl) {     // sigmoid given z*log2e
    return rcp1p(ex2f(-zl));
}
__device__ __forceinline__ float sigmoid_safe(float z) {
    z = fminf(fmaxf(z, -30.0f), 30.0f);
    return rcp1p(ex2f(-z * LOG2E));
}

// ---------------- kernel 1: precompute d (fp16) + fused iteration 0 ----------
// 512 blocks x 256 threads. Block owns 8 rows; thread owns 8 pair-columns.
__global__ void __launch_bounds__(256) pre_kernel(
    const float* __restrict__ S, const float* __restrict__ F)
{
    const int tid = threadIdx.x;
    const int rowBase = blockIdx.x * 8;
    const int b = rowBase >> 11;
    const int cp = tid * 8;
    const int lane = tid & 31, warp = tid >> 5;

    // s0c[j] = 1 - s1^0[col], computed locally from S
    float s0c[8];
#pragma unroll
    for (int j = 0; j < 8; j++) {
        int c = b * NN + cp + j;
        s0c[j] = 1.0f - sigmoid_safe(S[2 * c + 1] - S[2 * c]);
    }
    // m[r] = s1^0[row], computed locally
    float m[8];
#pragma unroll
    for (int r = 0; r < 8; r++) {
        int row = rowBase + r;
        m[r] = sigmoid_safe(S[2 * row + 1] - S[2 * row]);
    }

    float colsum[8] = {0, 0, 0, 0, 0, 0, 0, 0};
    __shared__ float sred[8][8];
    const float4* F4 = (const float4*)F;

#pragma unroll
    for (int r = 0; r < 8; r++) {
        const size_t row = rowBase + r;
        float4 f0 = F4[row * 1024 + tid * 4 + 0];
        float4 f1 = F4[row * 1024 + tid * 4 + 1];
        float4 f2 = F4[row * 1024 + tid * 4 + 2];
        float4 f3 = F4[row * 1024 + tid * 4 + 3];
        float zl[8];
        zl[0] = (f0.y - f0.x) * LOG2E; zl[1] = (f0.w - f0.z) * LOG2E;
        zl[2] = (f1.y - f1.x) * LOG2E; zl[3] = (f1.w - f1.z) * LOG2E;
        zl[4] = (f2.y - f2.x) * LOG2E; zl[5] = (f2.w - f2.z) * LOG2E;
        zl[6] = (f3.y - f3.x) * LOG2E; zl[7] = (f3.w - f3.z) * LOG2E;

        __half2 h0 = __floats2half2_rn(zl[0], zl[1]);
        __half2 h1 = __floats2half2_rn(zl[2], zl[3]);
        __half2 h2 = __floats2half2_rn(zl[4], zl[5]);
        __half2 h3 = __floats2half2_rn(zl[6], zl[7]);
        uint4 st;
        st.x = *(unsigned*)&h0; st.y = *(unsigned*)&h1;
        st.z = *(unsigned*)&h2; st.w = *(unsigned*)&h3;
        *(uint4*)&g_d[row * NN + cp] = st;

        float racc = 0.0f;
#pragma unroll
        for (int j = 0; j < 8; j++) {
            float q = sigl(zl[j]);
            racc = fmaf(q, s0c[j], racc);
            colsum[j] = fmaf(q, m[r], colsum[j]);
        }
        racc += __shfl_down_sync(~0u, racc, 16);
        racc += __shfl_down_sync(~0u, racc, 8);
        racc += __shfl_down_sync(~0u, racc, 4);
        racc += __shfl_down_sync(~0u, racc, 2);
        racc += __shfl_down_sync(~0u, racc, 1);
        if (lane == 0) sred[r][warp] = racc;
    }
    __syncthreads();
    if (tid < 8) {
        float v = 0.0f;
#pragma unroll
        for (int w = 0; w < 8; w++) v += sred[tid][w];
        g_A[rowBase + tid] = v;
    }
#pragma unroll
    for (int j = 0; j < 8; j++)
        atomicAdd(&g_Bv[b * NN + cp + j], colsum[j]);
}

// ---------------- node update (after iter k): s1^{k+1}; zero Bv -------------
__global__ void __launch_bounds__(512) node_kernel(
    const float* __restrict__ S, const float* __restrict__ C,
    const float* __restrict__ W, int k)
{
    const int i = blockIdx.x * 512 + threadIdx.x;
    const float w0 = W[0], w1 = W[1];
    const float Sd = S[2 * i + 1] - S[2 * i];
    const float Cd = C[2 * i] - C[2 * i + 1];
    float c0k;
    if (k == 0) {
        c0k = sigmoid_safe(Cd);
        g_s1[0][i] = sigmoid_safe(Sd);           // s1^0 table for iter 1
    } else {
        float s1km1 = g_s1[(k + 1) & 1][i];      // s1^{k-1}
        c0k = sigmoid_safe(Cd - w0 * s1km1);
    }
    float s1n = sigmoid_safe(Sd + w1 * g_Bv[i] - w0 * c0k - w1 * g_A[i]);
    g_s1[(k + 1) & 1][i] = s1n;                  // s1^{k+1}
    g_Bv[i] = 0.0f;                              // ready for next accumulation
}

// ---------------- iteration kernel (k = 1..4): A,Bv from fp16 d --------------
__global__ void __launch_bounds__(256) iter_kernel(
    const float* __restrict__ W, int k)
{
    const int tid = threadIdx.x;
    const int rowBase = blockIdx.x * 8;
    const int b = rowBase >> 11;
    const int cp = tid * 8;
    const int cur = k & 1, prv = cur ^ 1;
    const int lane = tid & 31, warp = tid >> 5;
    const float w1l = W[1] * LOG2E;

    float s0c[8], s0p[8];
    {
        float4 c0 = *(const float4*)&g_s1[cur][b * NN + cp];
        float4 c1 = *(const float4*)&g_s1[cur][b * NN + cp + 4];
        float4 p0 = *(const float4*)&g_s1[prv][b * NN + cp];
        float4 p1 = *(const float4*)&g_s1[prv][b * NN + cp + 4];
        s0c[0] = 1.f - c0.x; s0c[1] = 1.f - c0.y; s0c[2] = 1.f - c0.z; s0c[3] = 1.f - c0.w;
        s0c[4] = 1.f - c1.x; s0c[5] = 1.f - c1.y; s0c[6] = 1.f - c1.z; s0c[7] = 1.f - c1.w;
        s0p[0] = 1.f - p0.x; s0p[1] = 1.f - p0.y; s0p[2] = 1.f - p0.z; s0p[3] = 1.f - p0.w;
        s0p[4] = 1.f - p1.x; s0p[5] = 1.f - p1.y; s0p[6] = 1.f - p1.z; s0p[7] = 1.f - p1.w;
    }
    float a2[8], m[8];
#pragma unroll
    for (int r = 0; r < 8; r++) {
        a2[r] = w1l * g_s1[prv][rowBase + r];
        m[r]  = g_s1[cur][rowBase + r];
    }

    float colsum[8] = {0, 0, 0, 0, 0, 0, 0, 0};
    __shared__ float sred[8][8];

#pragma unroll
    for (int r = 0; r < 8; r++) {
        const size_t row = rowBase + r;
        uint4 dv = *(const uint4*)&g_d[row * NN + cp];
        float2 d01 = __half22float2(*(__half2*)&dv.x);
        float2 d23 = __half22float2(*(__half2*)&dv.y);
        float2 d45 = __half22float2(*(__half2*)&dv.z);
        float2 d67 = __half22float2(*(__half2*)&dv.w);
        float dd[8] = {d01.x, d01.y, d23.x, d23.y, d45.x, d45.y, d67.x, d67.y};
        float racc = 0.0f;
#pragma unroll
        for (int j = 0; j < 8; j++) {
            float q = rcp1p(ex2f(fmaf(a2[r], s0p[j], -dd[j])));
            racc = fmaf(q, s0c[j], racc);
            colsum[j] = fmaf(q, m[r], colsum[j]);
        }
        racc += __shfl_down_sync(~0u, racc, 16);
        racc += __shfl_down_sync(~0u, racc, 8);
        racc += __shfl_down_sync(~0u, racc, 4);
        racc += __shfl_down_sync(~0u, racc, 2);
        racc += __shfl_down_sync(~0u, racc, 1);
        if (lane == 0) sred[r][warp] = racc;
    }
    __syncthreads();
    if (tid < 8) {
        float v = 0.0f;
#pragma unroll
        for (int w = 0; w < 8; w++) v += sred[tid][w];
        g_A[rowBase + tid] = v;
    }
#pragma unroll
    for (int j = 0; j < 8; j++)
        atomicAdd(&g_Bv[b * NN + cp + j], colsum[j]);
}

// ---------------- final outputs ----------------------------------------------
// out layout (floats): [S: 8192][C: 8192][F: 16777216]
// s1^4 is g_s1[0], s1^3 is g_s1[1]; A/Bv hold iteration-4 sums.
__global__ void __launch_bounds__(256) final_kernel(
    const float* __restrict__ S, const float* __restrict__ C,
    const float* __restrict__ F, const float* __restrict__ W,
    float* __restrict__ out)
{
    const int row = blockIdx.x;
    const int b = row >> 11;
    const int tid = threadIdx.x;
    const float w0 = W[0], w1 = W[1];
    const float a = w1 * g_s1[0][row];
    const float4* Fr = (const float4*)F + (size_t)row * 1024;
    float4* Or = (float4*)out + 4096 + (size_t)row * 1024;
    const float* s1col = &g_s1[0][b * NN];

    float4 f[4]; float2 s[4];
#pragma unroll
    for (int u = 0; u < 4; u++) {
        int i = tid + 256 * u;
        f[u] = Fr[i];
        s[u] = *(const float2*)&s1col[2 * i];
    }
#pragma unroll
    for (int u = 0; u < 4; u++) {
        int i = tid + 256 * u;
        f[u].x = fmaf(a, 1.0f - s[u].x, f[u].x);
        f[u].z = fmaf(a, 1.0f - s[u].y, f[u].z);
        Or[i] = f[u];
    }
    if (row < 16) {
        int i = row * 256 + tid;
        float s13 = g_s1[1][i], s14 = g_s1[0][i];
        float Cd = C[2 * i] - C[2 * i + 1];
        float c04 = sigmoid_safe(Cd - w0 * s13);
        out[2 * i]     = S[2 * i] + w0 * c04 + w1 * g_A[i];
        out[2 * i + 1] = S[2 * i + 1] + w1 * g_Bv[i];
        out[8192 + 2 * i]     = C[2 * i];
        out[8192 + 2 * i + 1] = C[2 * i + 1] + w0 * s14;
        g_Bv[i] = 0.0f;                          // replay-safe reset
    }
}

extern "C" void kernel_launch(void* const* d_in, const int* in_sizes, int n_in,
                              void* d_out, int out_size)
{
    const float* S = (const float*)d_in[0];
    const float* C = (const float*)d_in[1];
    const float* F = (const float*)d_in[2];
    const float* W = (const float*)d_in[3];
    float* out = (float*)d_out;

    pre_kernel<<<512, 256>>>(S, F);              // d + iteration 0
    node_kernel<<<8, 512>>>(S, C, W, 0);
    for (int k = 1; k <= 4; k++) {
        iter_kernel<<<512, 256>>>(W, k);
        if (k < 4) node_kernel<<<8, 512>>>(S, C, W, k);
    }
    final_kernel<<<4096, 256>>>(S, C, F, W, out);
}

// round 4
// speedup vs baseline: 2.6728x; 2.6728x over previous
#include <cuda_runtime.h>
#include <cuda_fp16.h>
#include <cstdint>

#define NN     2048
#define NODES  4096
#define NBLK   512                    // pre/iter blocks; 8 rows per block
#define LOG2E  1.4426950408889634f

// ---------------- device scratch ----------------
__device__ __align__(16) __half g_d[(size_t)NODES * NN];  // (F1-F0)*log2e fp16, 16.8MB
__device__ __align__(16) float  g_s1[2][NODES];           // s1 ping-pong
__device__ __align__(16) float  g_A[NODES];               // row sums
__device__ __align__(16) float  g_Bv[NODES];              // reduced column sums
__device__ __align__(16) float  g_BvP[NBLK][NN];          // per-block column partials (4MB)

__device__ __forceinline__ float ex2f(float x) {
    float r; asm("ex2.approx.f32 %0, %1;" : "=f"(r) : "f"(x)); return r;
}
// 1/(1+u), u>=0 finite (magic seed + 2 Newton, rel err ~1.4e-6)
__device__ __forceinline__ float rcp1p(float u) {
    float den = 1.0f + u;
    float r = __uint_as_float(0x7ef311c3u - __float_as_uint(den));
    r = r * (2.0f - den * r);
    r = r * (2.0f - den * r);
    return r;
}
__device__ __forceinline__ float sigl(float zl) { return rcp1p(ex2f(-zl)); }
__device__ __forceinline__ float sigmoid_safe(float z) {
    z = fminf(fmaxf(z, -30.0f), 30.0f);
    return rcp1p(ex2f(-z * LOG2E));
}

// ---------------- pre: d=(F1-F0)*log2e (fp16) + fused iteration 0 ------------
// 512 blocks x 256 threads; block = 8 rows, thread = 8 columns.
__global__ void __launch_bounds__(256) pre_kernel(
    const float* __restrict__ S, const float* __restrict__ F)
{
    const int tid = threadIdx.x;
    const int rowBase = blockIdx.x * 8;
    const int b = rowBase >> 11;
    const int cp = tid * 8;
    const int lane = tid & 31, warp = tid >> 5;

    float s0c[8], m[8];
#pragma unroll
    for (int j = 0; j < 8; j++) {
        int c = b * NN + cp + j;
        s0c[j] = 1.0f - sigmoid_safe(S[2 * c + 1] - S[2 * c]);
    }
#pragma unroll
    for (int r = 0; r < 8; r++) {
        int row = rowBase + r;
        m[r] = sigmoid_safe(S[2 * row + 1] - S[2 * row]);
    }

    float colsum[8] = {0,0,0,0,0,0,0,0};
    float racc[8];
    const float4* F4 = (const float4*)F;

#pragma unroll 2
    for (int r = 0; r < 8; r++) {
        const size_t row = rowBase + r;
        // front-batch 4 independent 16B loads
        float4 f0 = F4[row * 1024 + tid * 4 + 0];
        float4 f1 = F4[row * 1024 + tid * 4 + 1];
        float4 f2 = F4[row * 1024 + tid * 4 + 2];
        float4 f3 = F4[row * 1024 + tid * 4 + 3];
        float zl[8];
        zl[0] = (f0.y - f0.x) * LOG2E; zl[1] = (f0.w - f0.z) * LOG2E;
        zl[2] = (f1.y - f1.x) * LOG2E; zl[3] = (f1.w - f1.z) * LOG2E;
        zl[4] = (f2.y - f2.x) * LOG2E; zl[5] = (f2.w - f2.z) * LOG2E;
        zl[6] = (f3.y - f3.x) * LOG2E; zl[7] = (f3.w - f3.z) * LOG2E;

        __half2 h0 = __floats2half2_rn(zl[0], zl[1]);
        __half2 h1 = __floats2half2_rn(zl[2], zl[3]);
        __half2 h2 = __floats2half2_rn(zl[4], zl[5]);
        __half2 h3 = __floats2half2_rn(zl[6], zl[7]);
        uint4 st;
        st.x = *(unsigned*)&h0; st.y = *(unsigned*)&h1;
        st.z = *(unsigned*)&h2; st.w = *(unsigned*)&h3;
        *(uint4*)&g_d[row * NN + cp] = st;

        float ra = 0.0f;
#pragma unroll
        for (int j = 0; j < 8; j++) {
            float q = sigl(zl[j]);
            ra = fmaf(q, s0c[j], ra);
            colsum[j] = fmaf(q, m[r], colsum[j]);
        }
        racc[r] = ra;
    }

    __shared__ float sred[8][8];
#pragma unroll
    for (int r = 0; r < 8; r++) {
        float v = racc[r];
        v += __shfl_down_sync(~0u, v, 16);
        v += __shfl_down_sync(~0u, v, 8);
        v += __shfl_down_sync(~0u, v, 4);
        v += __shfl_down_sync(~0u, v, 2);
        v += __shfl_down_sync(~0u, v, 1);
        if (lane == 0) sred[r][warp] = v;
    }
    __syncthreads();
    if (tid < 8) {
        float v = 0.0f;
#pragma unroll
        for (int w = 0; w < 8; w++) v += sred[tid][w];
        g_A[rowBase + tid] = v;
    }
    // plain coalesced partial stores (NO atomics)
    *(float4*)&g_BvP[blockIdx.x][cp]     = make_float4(colsum[0], colsum[1], colsum[2], colsum[3]);
    *(float4*)&g_BvP[blockIdx.x][cp + 4] = make_float4(colsum[4], colsum[5], colsum[6], colsum[7]);
}

// ---------------- iter k=1..4: A,BvP from fp16 d ------------------------------
__global__ void __launch_bounds__(256) iter_kernel(
    const float* __restrict__ W, int k)
{
    const int tid = threadIdx.x;
    const int rowBase = blockIdx.x * 8;
    const int b = rowBase >> 11;
    const int cp = tid * 8;
    const int cur = k & 1, prv = cur ^ 1;
    const int lane = tid & 31, warp = tid >> 5;
    const float w1l = W[1] * LOG2E;

    float s0c[8], s0p[8];
    {
        float4 c0 = *(const float4*)&g_s1[cur][b * NN + cp];
        float4 c1 = *(const float4*)&g_s1[cur][b * NN + cp + 4];
        float4 p0 = *(const float4*)&g_s1[prv][b * NN + cp];
        float4 p1 = *(const float4*)&g_s1[prv][b * NN + cp + 4];
        s0c[0]=1.f-c0.x; s0c[1]=1.f-c0.y; s0c[2]=1.f-c0.z; s0c[3]=1.f-c0.w;
        s0c[4]=1.f-c1.x; s0c[5]=1.f-c1.y; s0c[6]=1.f-c1.z; s0c[7]=1.f-c1.w;
        s0p[0]=1.f-p0.x; s0p[1]=1.f-p0.y; s0p[2]=1.f-p0.z; s0p[3]=1.f-p0.w;
        s0p[4]=1.f-p1.x; s0p[5]=1.f-p1.y; s0p[6]=1.f-p1.z; s0p[7]=1.f-p1.w;
    }
    float a2[8], m[8];
#pragma unroll
    for (int r = 0; r < 8; r++) {
        a2[r] = w1l * g_s1[prv][rowBase + r];
        m[r]  = g_s1[cur][rowBase + r];
    }

    // front-batch ALL 8 row loads (MLP=8)
    uint4 dv[8];
    const __half* dp = g_d + (size_t)rowBase * NN + cp;
#pragma unroll
    for (int r = 0; r < 8; r++)
        dv[r] = *(const uint4*)(dp + (size_t)r * NN);

    float colsum[8] = {0,0,0,0,0,0,0,0};
    float racc[8];
#pragma unroll
    for (int r = 0; r < 8; r++) {
        float2 d01 = __half22float2(*(__half2*)&dv[r].x);
        float2 d23 = __half22float2(*(__half2*)&dv[r].y);
        float2 d45 = __half22float2(*(__half2*)&dv[r].z);
        float2 d67 = __half22float2(*(__half2*)&dv[r].w);
        float dd[8] = {d01.x, d01.y, d23.x, d23.y, d45.x, d45.y, d67.x, d67.y};
        float ra = 0.0f;
#pragma unroll
        for (int j = 0; j < 8; j++) {
            float q = rcp1p(ex2f(fmaf(a2[r], s0p[j], -dd[j])));
            ra = fmaf(q, s0c[j], ra);
            colsum[j] = fmaf(q, m[r], colsum[j]);
        }
        racc[r] = ra;
    }

    __shared__ float sred[8][8];
#pragma unroll
    for (int r = 0; r < 8; r++) {
        float v = racc[r];
        v += __shfl_down_sync(~0u, v, 16);
        v += __shfl_down_sync(~0u, v, 8);
        v += __shfl_down_sync(~0u, v, 4);
        v += __shfl_down_sync(~0u, v, 2);
        v += __shfl_down_sync(~0u, v, 1);
        if (lane == 0) sred[r][warp] = v;
    }
    __syncthreads();
    if (tid < 8) {
        float v = 0.0f;
#pragma unroll
        for (int w = 0; w < 8; w++) v += sred[tid][w];
        g_A[rowBase + tid] = v;
    }
    *(float4*)&g_BvP[blockIdx.x][cp]     = make_float4(colsum[0], colsum[1], colsum[2], colsum[3]);
    *(float4*)&g_BvP[blockIdx.x][cp + 4] = make_float4(colsum[4], colsum[5], colsum[6], colsum[7]);
}

// ---------------- node: reduce BvP -> Bv; update s1 (k<4) ---------------------
// grid 128 x 256. Block handles 32 consecutive nodes; 8 slices of 32 partials.
__global__ void __launch_bounds__(256) node_kernel(
    const float* __restrict__ S, const float* __restrict__ C,
    const float* __restrict__ W, int k)
{
    const int tid = threadIdx.x;
    const int node0 = blockIdx.x * 32;
    const int nl = tid & 31, slice = tid >> 5;
    const int node = node0 + nl;
    const int b = node >> 11, c = node & (NN - 1);

    // sum 32 partial rows (coalesced across lanes), front-batched by 8
    const float* P = &g_BvP[b * 256 + slice * 32][c];
    float sum = 0.0f;
#pragma unroll
    for (int j0 = 0; j0 < 32; j0 += 8) {
        float t0 = P[(j0 + 0) * NN], t1 = P[(j0 + 1) * NN];
        float t2 = P[(j0 + 2) * NN], t3 = P[(j0 + 3) * NN];
        float t4 = P[(j0 + 4) * NN], t5 = P[(j0 + 5) * NN];
        float t6 = P[(j0 + 6) * NN], t7 = P[(j0 + 7) * NN];
        sum += ((t0 + t1) + (t2 + t3)) + ((t4 + t5) + (t6 + t7));
    }
    __shared__ float sh[8][32];
    sh[slice][nl] = sum;
    __syncthreads();
    if (tid < 32) {
        const int i = node0 + tid;
        float v = 0.0f;
#pragma unroll
        for (int s = 0; s < 8; s++) v += sh[s][tid];
        g_Bv[i] = v;
        if (k < 4) {
            const float w0 = W[0], w1 = W[1];
            const float Sd = S[2 * i + 1] - S[2 * i];
            const float Cd = C[2 * i] - C[2 * i + 1];
            float s1km1 = g_s1[(k + 1) & 1][i];           // s1^{k-1}
            float c0k = (k == 0) ? sigmoid_safe(Cd)
                                 : sigmoid_safe(Cd - w0 * s1km1);
            float s1n = sigmoid_safe(Sd + w1 * v - w0 * c0k - w1 * g_A[i]);
            if (k == 0) g_s1[0][i] = sigmoid_safe(Sd);    // s1^0 table
            g_s1[(k + 1) & 1][i] = s1n;                   // s1^{k+1}
        }
    }
}

// ---------------- final outputs -----------------------------------------------
// out floats: [S: 8192][C: 8192][F: 16777216]; s1^4 = g_s1[0], s1^3 = g_s1[1]
__global__ void __launch_bounds__(256) final_kernel(
    const float* __restrict__ S, const float* __restrict__ C,
    const float* __restrict__ F, const float* __restrict__ W,
    float* __restrict__ out)
{
    const int row = blockIdx.x;
    const int b = row >> 11;
    const int tid = threadIdx.x;
    const float w0 = W[0], w1 = W[1];
    const float a = w1 * g_s1[0][row];
    const float4* Fr = (const float4*)F + (size_t)row * 1024;
    float4* Or = (float4*)out + 4096 + (size_t)row * 1024;
    const float* s1col = &g_s1[0][b * NN];

    float4 f[4]; float2 s[4];
#pragma unroll
    for (int u = 0; u < 4; u++) {
        int i = tid + 256 * u;
        f[u] = Fr[i];
        s[u] = *(const float2*)&s1col[2 * i];
    }
#pragma unroll
    for (int u = 0; u < 4; u++) {
        int i = tid + 256 * u;
        f[u].x = fmaf(a, 1.0f - s[u].x, f[u].x);
        f[u].z = fmaf(a, 1.0f - s[u].y, f[u].z);
        Or[i] = f[u];
    }
    if (row < 16) {
        int i = row * 256 + tid;
        float s13 = g_s1[1][i], s14 = g_s1[0][i];
        float Cd = C[2 * i] - C[2 * i + 1];
        float c04 = sigmoid_safe(Cd - w0 * s13);
        out[2 * i]     = S[2 * i] + w0 * c04 + w1 * g_A[i];
        out[2 * i + 1] = S[2 * i + 1] + w1 * g_Bv[i];
        out[8192 + 2 * i]     = C[2 * i];
        out[8192 + 2 * i + 1] = C[2 * i + 1] + w0 * s14;
    }
}

extern "C" void kernel_launch(void* const* d_in, const int* in_sizes, int n_in,
                              void* d_out, int out_size)
{
    const float* S = (const float*)d_in[0];
    const float* C = (const float*)d_in[1];
    const float* F = (const float*)d_in[2];
    const float* W = (const float*)d_in[3];
    float* out = (float*)d_out;

    pre_kernel<<<NBLK, 256>>>(S, F);             // d + iteration 0 sums
    node_kernel<<<128, 256>>>(S, C, W, 0);
    for (int k = 1; k <= 4; k++) {
        iter_kernel<<<NBLK, 256>>>(W, k);
        node_kernel<<<128, 256>>>(S, C, W, k);   // k=4: Bv reduce only
    }
    final_kernel<<<4096, 256>>>(S, C, F, W, out);
}